// round 15
// baseline (speedup 1.0000x reference)
#include <cuda_runtime.h>
#include <cuda_fp16.h>
#include <cstdint>

#define NN   50000
#define EE   800000
#define HID  128
#define NG   64
#define ODIM 64

// ---------------- device scratch (no allocations allowed) ----------------
__device__ __half g_lbufH[NN * HID];  // x @ Wl^T, fp16 transport (edge-gathered); reused both layers
__device__ float  g_rbuf1[NN * HID];  // layer-1 self term (+bias)
__device__ float  g_rbuf2[NN * HID];  // layer-2 self term (+bias)
__device__ float  g_asum1[NN * HID];  // layer-1 neighbor sum (no self, no relu)
__device__ float  g_asum2[NN * HID];  // layer-2 neighbor sum
__device__ float  g_feat2[NN * HID];  // relu(asum2 + rbuf2) -> pool3 input
__device__ int    g_deg[NN];
__device__ int    g_rowptr[NN + 1];
__device__ int    g_cursor[NN];
__device__ int    g_csr_src[EE];
__device__ float  g_WT[4][HID * HID]; // transposed weights [in][out]: W1l,W1r,W2l,W2r
__device__ float  g_Pagg [NG * HID];
__device__ float  g_Pself[NG * HID];
__device__ float  g_cnt[NG];

// ---------------- packed f32x2 / half helpers ----------------
__device__ __forceinline__ uint64_t splat2(float v) {
    uint64_t r;
    asm("mov.b64 %0, {%1, %1};" : "=l"(r) : "f"(v));
    return r;
}
__device__ __forceinline__ uint64_t pk2(float x, float y) {
    uint64_t r;
    asm("mov.b64 %0, {%1, %2};" : "=l"(r) : "f"(x), "f"(y));
    return r;
}
__device__ __forceinline__ void ffma2(uint64_t& d, uint64_t a, uint64_t b) {
    asm("fma.rn.f32x2 %0, %1, %2, %0;" : "+l"(d) : "l"(a), "l"(b));
}
__device__ __forceinline__ float2 unpk2(uint64_t v) {
    float x, y;
    asm("mov.b64 {%0, %1}, %2;" : "=f"(x), "=f"(y) : "l"(v));
    return make_float2(x, y);
}
__device__ __forceinline__ float4 h4_to_f4(uint2 u) {
    __half2 h0 = *(__half2*)&u.x, h1 = *(__half2*)&u.y;
    float2 f0 = __half22float2(h0), f1 = __half22float2(h1);
    return make_float4(f0.x, f0.y, f1.x, f1.y);
}
__device__ __forceinline__ uint2 f4_to_h4(float4 v) {
    union { __half2 h[2]; uint2 u; } c;
    c.h[0] = __floats2half2_rn(v.x, v.y);
    c.h[1] = __floats2half2_rn(v.z, v.w);
    return c.u;
}

// ---------------- weight transposes ----------------
__global__ void k_tr(const float* __restrict__ W1l, const float* __restrict__ W1r,
                     const float* __restrict__ W2l, const float* __restrict__ W2r) {
    int i = blockIdx.x * blockDim.x + threadIdx.x;   // 65536 threads
    int idx = i >> 14;
    int r = i & (HID * HID - 1);
    int o = r / HID, k = r % HID;
    const float* W = (idx == 0) ? W1l : (idx == 1) ? W1r : (idx == 2) ? W2l : W2r;
    g_WT[idx][k * HID + o] = W[o * HID + k];
}

// ---------------- zero counters (side stream) ----------------
__global__ void k_zero2() {
    int i = blockIdx.x * blockDim.x + threadIdx.x;
    if (i < NN) g_deg[i] = 0;
    if (i < NG * HID) { g_Pagg[i] = 0.f; g_Pself[i] = 0.f; }
    if (i < NG) g_cnt[i] = 0.f;
}

__global__ void k_hist(const int* __restrict__ dst) {
    int t = blockIdx.x * blockDim.x + threadIdx.x;
    int e = t * 4;
    if (e + 3 < EE) {
        int4 d = *(const int4*)(dst + e);
        atomicAdd(&g_deg[d.x], 1);
        atomicAdd(&g_deg[d.y], 1);
        atomicAdd(&g_deg[d.z], 1);
        atomicAdd(&g_deg[d.w], 1);
    } else {
        for (int q = e; q < EE; q++) atomicAdd(&g_deg[dst[q]], 1);
    }
}

__global__ void k_scan() {
    __shared__ int ssum[1024];
    int tid = threadIdx.x;
    const int CH = (NN + 1023) / 1024;
    int base = tid * CH;
    int s = 0;
    for (int i = 0; i < CH; i++) { int idx = base + i; if (idx < NN) s += g_deg[idx]; }
    ssum[tid] = s;
    __syncthreads();
    for (int off = 1; off < 1024; off <<= 1) {
        int v = (tid >= off) ? ssum[tid - off] : 0;
        __syncthreads();
        ssum[tid] += v;
        __syncthreads();
    }
    int run = (tid == 0) ? 0 : ssum[tid - 1];
    for (int i = 0; i < CH; i++) {
        int idx = base + i;
        if (idx < NN) { g_rowptr[idx] = run; g_cursor[idx] = run; run += g_deg[idx]; }
    }
    if (tid == 1023) g_rowptr[NN] = run;
}

__global__ void k_bin(const int* __restrict__ src, const int* __restrict__ dst) {
    int t = blockIdx.x * blockDim.x + threadIdx.x;
    int e = t * 2;
    if (e + 1 < EE) {
        int2 s = *(const int2*)(src + e);
        int2 d = *(const int2*)(dst + e);
        int p0 = atomicAdd(&g_cursor[d.x], 1);
        g_csr_src[p0] = s.x;
        int p1 = atomicAdd(&g_cursor[d.y], 1);
        g_csr_src[p1] = s.y;
    } else if (e < EE) {
        int p = atomicAdd(&g_cursor[dst[e]], 1);
        g_csr_src[p] = src[e];
    }
}

// ---------------- fp32 GEMM, single half per launch ----------------
// asel: -1 -> A = Aext (x) ; 1 -> A[n] = relu(asum1[n] + rbuf1[n]) (fused layer-1 epilogue)
// hf:   0 -> out = lbufH (fp16, no bias) ; 1 -> out = rbuf (fp32, +bias); rsel picks rbuf1/rbuf2
__global__ __launch_bounds__(256) void k_gemm(
    const float* __restrict__ Aext, int asel,
    int wt, const float* __restrict__ bias, int hf, int rsel)
{
    const float* __restrict__ BT = g_WT[wt];
    float* __restrict__ ROUT = rsel ? g_rbuf2 : g_rbuf1;

    __shared__ float As[16][128];
    __shared__ float Bs[16][128];

    int tid = threadIdx.x;
    int tx = tid & 15;
    int ty = tid >> 4;
    int m0 = blockIdx.x * 128;

    uint64_t acc[8][4];
    uint64_t z = splat2(0.f);
#pragma unroll
    for (int i = 0; i < 8; i++)
#pragma unroll
        for (int j = 0; j < 4; j++) acc[i][j] = z;

    int arow = tid & 127;
    int akq0 = tid >> 7;
    int bj   = (tid & 31) * 4;
    int bk0  = tid >> 5;
    int grow = m0 + arow;

    for (int k0 = 0; k0 < 128; k0 += 16) {
#pragma unroll
        for (int p = 0; p < 2; p++) {
            int kq = akq0 + p * 2;
            float4 v = make_float4(0.f, 0.f, 0.f, 0.f);
            if (grow < NN) {
                size_t off = (size_t)grow * HID + k0 + kq * 4;
                if (asel < 0) {
                    v = *(const float4*)(Aext + off);
                } else {
                    float4 a = *(const float4*)(g_asum1 + off);
                    float4 r = *(const float4*)(g_rbuf1 + off);
                    v.x = fmaxf(a.x + r.x, 0.f);
                    v.y = fmaxf(a.y + r.y, 0.f);
                    v.z = fmaxf(a.z + r.z, 0.f);
                    v.w = fmaxf(a.w + r.w, 0.f);
                }
            }
            As[kq * 4 + 0][arow] = v.x;
            As[kq * 4 + 1][arow] = v.y;
            As[kq * 4 + 2][arow] = v.z;
            As[kq * 4 + 3][arow] = v.w;
        }
#pragma unroll
        for (int p = 0; p < 2; p++) {
            int kr = bk0 + p * 8;
            *(float4*)&Bs[kr][bj] = *(const float4*)(BT + (size_t)(k0 + kr) * HID + bj);
        }
        __syncthreads();
#pragma unroll
        for (int kk = 0; kk < 16; kk++) {
            float a[8];
            *(float4*)&a[0] = *(const float4*)&As[kk][ty * 8];
            *(float4*)&a[4] = *(const float4*)&As[kk][ty * 8 + 4];
            float4 bl = *(const float4*)&Bs[kk][tx * 4];
            float4 bh = *(const float4*)&Bs[kk][64 + tx * 4];
            uint64_t bp[4];
            bp[0] = pk2(bl.x, bl.y); bp[1] = pk2(bl.z, bl.w);
            bp[2] = pk2(bh.x, bh.y); bp[3] = pk2(bh.z, bh.w);
#pragma unroll
            for (int i = 0; i < 8; i++) {
                uint64_t as_ = splat2(a[i]);
                ffma2(acc[i][0], as_, bp[0]);
                ffma2(acc[i][1], as_, bp[1]);
                ffma2(acc[i][2], as_, bp[2]);
                ffma2(acc[i][3], as_, bp[3]);
            }
        }
        __syncthreads();
    }

    float bv0[4], bv1[4];
#pragma unroll
    for (int j = 0; j < 4; j++) {
        bv0[j] = hf ? bias[tx * 4 + j] : 0.f;
        bv1[j] = hf ? bias[64 + tx * 4 + j] : 0.f;
    }
#pragma unroll
    for (int i = 0; i < 8; i++) {
        int gr = m0 + ty * 8 + i;
        if (gr >= NN) continue;
        float2 p0 = unpk2(acc[i][0]), p1 = unpk2(acc[i][1]);
        float2 p2 = unpk2(acc[i][2]), p3 = unpk2(acc[i][3]);
        float4 v0 = make_float4(p0.x + bv0[0], p0.y + bv0[1], p1.x + bv0[2], p1.y + bv0[3]);
        float4 v1 = make_float4(p2.x + bv1[0], p2.y + bv1[1], p3.x + bv1[2], p3.y + bv1[3]);
        if (hf) {
            *(float4*)(ROUT + (size_t)gr * HID + tx * 4)      = v0;
            *(float4*)(ROUT + (size_t)gr * HID + 64 + tx * 4) = v1;
        } else {
            *(uint2*)(g_lbufH + (size_t)gr * HID + tx * 4)      = f4_to_h4(v0);
            *(uint2*)(g_lbufH + (size_t)gr * HID + 64 + tx * 4) = f4_to_h4(v1);
        }
    }
}

// ---------------- neighbor-sum only (no self, no relu): asum = sum lbufH[src] ----------------
__global__ void k_aggsum(int osel) {
    float* __restrict__ OUT = osel ? g_asum2 : g_asum1;
    int w    = (blockIdx.x * blockDim.x + threadIdx.x) >> 5;
    int lane = threadIdx.x & 31;
    if (w >= NN) return;
    int beg = g_rowptr[w], end = g_rowptr[w + 1];
    float4 acc = make_float4(0.f, 0.f, 0.f, 0.f);
    int e = beg;
    for (; e + 3 < end; e += 4) {
        int s0 = g_csr_src[e], s1 = g_csr_src[e + 1];
        int s2 = g_csr_src[e + 2], s3 = g_csr_src[e + 3];
        float4 v0 = h4_to_f4(*(const uint2*)(g_lbufH + (size_t)s0 * HID + lane * 4));
        float4 v1 = h4_to_f4(*(const uint2*)(g_lbufH + (size_t)s1 * HID + lane * 4));
        float4 v2 = h4_to_f4(*(const uint2*)(g_lbufH + (size_t)s2 * HID + lane * 4));
        float4 v3 = h4_to_f4(*(const uint2*)(g_lbufH + (size_t)s3 * HID + lane * 4));
        acc.x += (v0.x + v1.x) + (v2.x + v3.x);
        acc.y += (v0.y + v1.y) + (v2.y + v3.y);
        acc.z += (v0.z + v1.z) + (v2.z + v3.z);
        acc.w += (v0.w + v1.w) + (v2.w + v3.w);
    }
    for (; e < end; e++) {
        int s0 = g_csr_src[e];
        float4 v0 = h4_to_f4(*(const uint2*)(g_lbufH + (size_t)s0 * HID + lane * 4));
        acc.x += v0.x; acc.y += v0.y; acc.z += v0.z; acc.w += v0.w;
    }
    *(float4*)(OUT + (size_t)w * HID + lane * 4) = acc;
}

// ---------------- fuse: feat2 = relu(asum2 + rbuf2) ----------------
__global__ void k_fuse2() {
    int i = blockIdx.x * blockDim.x + threadIdx.x;   // one float4 per thread
    if (i >= NN * HID / 4) return;
    float4 a = ((const float4*)g_asum2)[i];
    float4 r = ((const float4*)g_rbuf2)[i];
    float4 v;
    v.x = fmaxf(a.x + r.x, 0.f);
    v.y = fmaxf(a.y + r.y, 0.f);
    v.z = fmaxf(a.z + r.z, 0.f);
    v.w = fmaxf(a.w + r.w, 0.f);
    ((float4*)g_feat2)[i] = v;
}

// ---------------- layer-3 collapsed per-graph reduction (fp32 feat2, NPW=16) ----------------
__global__ void k_pool3(const int* __restrict__ batch) {
    const float* __restrict__ h = g_feat2;
    const int NPW = 16;
    int w    = (blockIdx.x * blockDim.x + threadIdx.x) >> 5;
    int lane = threadIdx.x & 31;
    int n0 = w * NPW;
    if (n0 >= NN) return;
    int n1 = min(n0 + NPW, NN);

    float4 aS = make_float4(0.f, 0.f, 0.f, 0.f);
    float4 aA = make_float4(0.f, 0.f, 0.f, 0.f);
    int cg = -1, cnt = 0;
    for (int n = n0; n < n1; n++) {
        int g = batch[n];
        if (g != cg) {
            if (cg >= 0) {
                float* ps = g_Pself + cg * HID + lane * 4;
                float* pa = g_Pagg  + cg * HID + lane * 4;
                atomicAdd(ps + 0, aS.x); atomicAdd(ps + 1, aS.y);
                atomicAdd(ps + 2, aS.z); atomicAdd(ps + 3, aS.w);
                atomicAdd(pa + 0, aA.x); atomicAdd(pa + 1, aA.y);
                atomicAdd(pa + 2, aA.z); atomicAdd(pa + 3, aA.w);
                if (lane == 0) atomicAdd(&g_cnt[cg], (float)cnt);
            }
            cg = g; cnt = 0;
            aS = make_float4(0.f, 0.f, 0.f, 0.f);
            aA = make_float4(0.f, 0.f, 0.f, 0.f);
        }
        float4 v = *(const float4*)(h + (size_t)n * HID + lane * 4);
        aS.x += v.x; aS.y += v.y; aS.z += v.z; aS.w += v.w;
        cnt++;
        int beg = g_rowptr[n], end = g_rowptr[n + 1];
        int e = beg;
        for (; e + 3 < end; e += 4) {
            int s0 = g_csr_src[e], s1 = g_csr_src[e + 1];
            int s2 = g_csr_src[e + 2], s3 = g_csr_src[e + 3];
            float4 u0 = *(const float4*)(h + (size_t)s0 * HID + lane * 4);
            float4 u1 = *(const float4*)(h + (size_t)s1 * HID + lane * 4);
            float4 u2 = *(const float4*)(h + (size_t)s2 * HID + lane * 4);
            float4 u3 = *(const float4*)(h + (size_t)s3 * HID + lane * 4);
            aA.x += (u0.x + u1.x) + (u2.x + u3.x);
            aA.y += (u0.y + u1.y) + (u2.y + u3.y);
            aA.z += (u0.z + u1.z) + (u2.z + u3.z);
            aA.w += (u0.w + u1.w) + (u2.w + u3.w);
        }
        for (; e < end; e++) {
            int s0 = g_csr_src[e];
            float4 u0 = *(const float4*)(h + (size_t)s0 * HID + lane * 4);
            aA.x += u0.x; aA.y += u0.y; aA.z += u0.z; aA.w += u0.w;
        }
    }
    if (cg >= 0) {
        float* ps = g_Pself + cg * HID + lane * 4;
        float* pa = g_Pagg  + cg * HID + lane * 4;
        atomicAdd(ps + 0, aS.x); atomicAdd(ps + 1, aS.y);
        atomicAdd(ps + 2, aS.z); atomicAdd(ps + 3, aS.w);
        atomicAdd(pa + 0, aA.x); atomicAdd(pa + 1, aA.y);
        atomicAdd(pa + 2, aA.z); atomicAdd(pa + 3, aA.w);
        if (lane == 0) atomicAdd(&g_cnt[cg], (float)cnt);
    }
}

// ---------------- final: pooled = (Pagg@W3l^T + cnt*b3l + Pself@W3r^T)/cnt ; out = pooled@Wlin^T + blin
__global__ void k_final3(const float* __restrict__ W3l, const float* __restrict__ b3l,
                         const float* __restrict__ W3r,
                         const float* __restrict__ Wlin, const float* __restrict__ blin,
                         float* __restrict__ out) {
    __shared__ float sA[HID], sS[HID], sP[HID];
    int g = blockIdx.x, t = threadIdx.x;
    sA[t] = g_Pagg [g * HID + t];
    sS[t] = g_Pself[g * HID + t];
    __syncthreads();
    float cnt = g_cnt[g];
    float inv = 1.f / fmaxf(cnt, 1.f);
    float s = cnt * b3l[t];
    const float* wl = W3l + t * HID;
    const float* wr = W3r + t * HID;
#pragma unroll
    for (int k = 0; k < HID; k++) s = fmaf(sA[k], wl[k], fmaf(sS[k], wr[k], s));
    sP[t] = s * inv;
    __syncthreads();
    if (t < ODIM) {
        float o = blin[t];
        const float* wf = Wlin + t * HID;
#pragma unroll
        for (int k = 0; k < HID; k++) o = fmaf(sP[k], wf[k], o);
        out[g * ODIM + t] = o;
    }
}

// ---------------- launch: split-GEMM dependency pipeline ----------------
static cudaStream_t g_s2 = nullptr;
static cudaEvent_t  g_e0 = nullptr, g_eCSR = nullptr, g_eG1L = nullptr,
                    g_eG1R = nullptr, g_eG2L = nullptr, g_eG2R = nullptr;

extern "C" void kernel_launch(void* const* d_in, const int* in_sizes, int n_in,
                              void* d_out, int out_size) {
    const float* x    = (const float*)d_in[0];
    const int*   ei   = (const int*)d_in[1];
    const int*   batch= (const int*)d_in[2];
    const float* W1l  = (const float*)d_in[3];
    const float* b1l  = (const float*)d_in[4];
    const float* W1r  = (const float*)d_in[5];
    const float* W2l  = (const float*)d_in[6];
    const float* b2l  = (const float*)d_in[7];
    const float* W2r  = (const float*)d_in[8];
    const float* W3l  = (const float*)d_in[9];
    const float* b3l  = (const float*)d_in[10];
    const float* W3r  = (const float*)d_in[11];
    const float* Wlin = (const float*)d_in[12];
    const float* blin = (const float*)d_in[13];
    float* out = (float*)d_out;

    const int* src = ei;
    const int* dst = ei + EE;

    if (!g_s2) {
        cudaStreamCreateWithFlags(&g_s2, cudaStreamNonBlocking);
        cudaEventCreateWithFlags(&g_e0,   cudaEventDisableTiming);
        cudaEventCreateWithFlags(&g_eCSR, cudaEventDisableTiming);
        cudaEventCreateWithFlags(&g_eG1L, cudaEventDisableTiming);
        cudaEventCreateWithFlags(&g_eG1R, cudaEventDisableTiming);
        cudaEventCreateWithFlags(&g_eG2L, cudaEventDisableTiming);
        cudaEventCreateWithFlags(&g_eG2R, cudaEventDisableTiming);
    }

    const int ZB = (NN + 255) / 256;
    const int AGG_B = (NN * 32 + 255) / 256;
    const int GB = (NN + 127) / 128;   // 391

    // fork: side stream builds CSR while main runs tr + G1-lbuf
    cudaEventRecord(g_e0, 0);
    cudaStreamWaitEvent(g_s2, g_e0, 0);
    k_zero2<<<ZB, 256, 0, g_s2>>>();
    k_hist<<<(EE / 4 + 255) / 256, 256, 0, g_s2>>>(dst);
    k_scan<<<1, 1024, 0, g_s2>>>();
    k_bin<<<(EE / 2 + 255) / 256, 256, 0, g_s2>>>(src, dst);
    cudaEventRecord(g_eCSR, g_s2);

    // main: transposes + G1-lbuf (x @ W1l -> lbufH)
    k_tr<<<256, 256>>>(W1l, W1r, W2l, W2r);
    k_gemm<<<GB, 256>>>(x, -1, 0, b1l, /*hf=*/0, 0);
    cudaEventRecord(g_eG1L, 0);

    // side: G1-rbuf (x @ W1r + b1l -> rbuf1), FMA-bound, overlaps aggsum-1
    cudaStreamWaitEvent(g_s2, g_eG1L, 0);
    k_gemm<<<GB, 256, 0, g_s2>>>(x, -1, 1, b1l, /*hf=*/1, /*rsel=*/0);
    cudaEventRecord(g_eG1R, g_s2);

    // main: aggsum-1 (needs CSR + lbufH), L2-bound, overlaps G1-rbuf
    cudaStreamWaitEvent(0, g_eCSR, 0);
    k_aggsum<<<AGG_B, 256>>>(0);

    // main: G2-lbuf with fused A = relu(asum1 + rbuf1)
    cudaStreamWaitEvent(0, g_eG1R, 0);
    k_gemm<<<GB, 256>>>(nullptr, 1, 2, b2l, /*hf=*/0, 0);
    cudaEventRecord(g_eG2L, 0);

    // side: G2-rbuf (fused A @ W2r + b2l -> rbuf2), overlaps aggsum-2
    cudaStreamWaitEvent(g_s2, g_eG2L, 0);
    k_gemm<<<GB, 256, 0, g_s2>>>(nullptr, 1, 3, b2l, /*hf=*/1, /*rsel=*/1);
    cudaEventRecord(g_eG2R, g_s2);

    // main: aggsum-2 (lbufH layer-2), overlaps G2-rbuf
    k_aggsum<<<AGG_B, 256>>>(1);

    // join + fuse + pool + final
    cudaStreamWaitEvent(0, g_eG2R, 0);
    k_fuse2<<<(NN * HID / 4 + 255) / 256, 256>>>();
    const int POOL_W = (NN + 15) / 16;
    const int POOL_B = (POOL_W * 32 + 255) / 256;
    k_pool3<<<POOL_B, 256>>>(batch);
    k_final3<<<NG, HID>>>(W3l, b3l, W3r, Wlin, blin, out);
}

// round 16
// speedup vs baseline: 1.2210x; 1.2210x over previous
#include <cuda_runtime.h>
#include <cuda_fp16.h>
#include <cstdint>

#define NN   50000
#define EE   800000
#define HID  128
#define NG   64
#define ODIM 64

// ---------------- device scratch (no allocations allowed) ----------------
__device__ __half g_lbufH[NN * HID];  // x @ Wl^T, fp16 transport (random-gathered over edges)
__device__ float  g_rbuf[NN * HID];   // x @ Wr^T + b, fp32
__device__ float  g_feat[NN * HID];   // activations, fp32
__device__ int    g_deg[NN];
__device__ int    g_rowptr[NN + 1];
__device__ int    g_cursor[NN];
__device__ int    g_csr_src[EE];
__device__ float  g_WT[4][HID * HID]; // transposed weights [in][out]: W1l,W1r,W2l,W2r
__device__ float  g_Pagg [NG * HID];
__device__ float  g_Pself[NG * HID];
__device__ float  g_cnt[NG];

// ---------------- packed f32x2 / half helpers ----------------
__device__ __forceinline__ uint64_t splat2(float v) {
    uint64_t r;
    asm("mov.b64 %0, {%1, %1};" : "=l"(r) : "f"(v));
    return r;
}
__device__ __forceinline__ uint64_t pk2(float x, float y) {
    uint64_t r;
    asm("mov.b64 %0, {%1, %2};" : "=l"(r) : "f"(x), "f"(y));
    return r;
}
__device__ __forceinline__ void ffma2(uint64_t& d, uint64_t a, uint64_t b) {
    asm("fma.rn.f32x2 %0, %1, %2, %0;" : "+l"(d) : "l"(a), "l"(b));
}
__device__ __forceinline__ float2 unpk2(uint64_t v) {
    float x, y;
    asm("mov.b64 {%0, %1}, %2;" : "=f"(x), "=f"(y) : "l"(v));
    return make_float2(x, y);
}
__device__ __forceinline__ float4 h4_to_f4(uint2 u) {
    __half2 h0 = *(__half2*)&u.x, h1 = *(__half2*)&u.y;
    float2 f0 = __half22float2(h0), f1 = __half22float2(h1);
    return make_float4(f0.x, f0.y, f1.x, f1.y);
}
__device__ __forceinline__ uint2 f4_to_h4(float4 v) {
    union { __half2 h[2]; uint2 u; } c;
    c.h[0] = __floats2half2_rn(v.x, v.y);
    c.h[1] = __floats2half2_rn(v.z, v.w);
    return c.u;
}

// ---------------- weight transposes (critical path, main stream) ----------------
__global__ void k_tr(const float* __restrict__ W1l, const float* __restrict__ W1r,
                     const float* __restrict__ W2l, const float* __restrict__ W2r) {
    int i = blockIdx.x * blockDim.x + threadIdx.x;   // 65536 threads
    int idx = i >> 14;
    int r = i & (HID * HID - 1);
    int o = r / HID, k = r % HID;
    const float* W = (idx == 0) ? W1l : (idx == 1) ? W1r : (idx == 2) ? W2l : W2r;
    g_WT[idx][k * HID + o] = W[o * HID + k];
}

// ---------------- zero counters (side stream) ----------------
__global__ void k_zero2() {
    int i = blockIdx.x * blockDim.x + threadIdx.x;
    if (i < NN) g_deg[i] = 0;
    if (i < NG * HID) { g_Pagg[i] = 0.f; g_Pself[i] = 0.f; }
    if (i < NG) g_cnt[i] = 0.f;
}

__global__ void k_hist(const int* __restrict__ dst) {
    int t = blockIdx.x * blockDim.x + threadIdx.x;
    int e = t * 4;
    if (e + 3 < EE) {
        int4 d = *(const int4*)(dst + e);
        atomicAdd(&g_deg[d.x], 1);
        atomicAdd(&g_deg[d.y], 1);
        atomicAdd(&g_deg[d.z], 1);
        atomicAdd(&g_deg[d.w], 1);
    } else {
        for (int q = e; q < EE; q++) atomicAdd(&g_deg[dst[q]], 1);
    }
}

__global__ void k_scan() {
    __shared__ int ssum[1024];
    int tid = threadIdx.x;
    const int CH = (NN + 1023) / 1024;
    int base = tid * CH;
    int s = 0;
    for (int i = 0; i < CH; i++) { int idx = base + i; if (idx < NN) s += g_deg[idx]; }
    ssum[tid] = s;
    __syncthreads();
    for (int off = 1; off < 1024; off <<= 1) {
        int v = (tid >= off) ? ssum[tid - off] : 0;
        __syncthreads();
        ssum[tid] += v;
        __syncthreads();
    }
    int run = (tid == 0) ? 0 : ssum[tid - 1];
    for (int i = 0; i < CH; i++) {
        int idx = base + i;
        if (idx < NN) { g_rowptr[idx] = run; g_cursor[idx] = run; run += g_deg[idx]; }
    }
    if (tid == 1023) g_rowptr[NN] = run;
}

__global__ void k_bin(const int* __restrict__ src, const int* __restrict__ dst) {
    int t = blockIdx.x * blockDim.x + threadIdx.x;
    int e = t * 2;
    if (e + 1 < EE) {
        int2 s = *(const int2*)(src + e);
        int2 d = *(const int2*)(dst + e);
        int p0 = atomicAdd(&g_cursor[d.x], 1);
        g_csr_src[p0] = s.x;
        int p1 = atomicAdd(&g_cursor[d.y], 1);
        g_csr_src[p1] = s.y;
    } else if (e < EE) {
        int p = atomicAdd(&g_cursor[dst[e]], 1);
        g_csr_src[p] = src[e];
    }
}

// ---------------- fp32 GEMM: [lbufH | rbuf] = A @ WT (+bias on rbuf half) ----------------
// M=NN, N=128 per half, K=128. Block tile 128x128, 256 threads, 8x8/thread.
__global__ __launch_bounds__(256) void k_gemm(
    const float* __restrict__ Aext, int asel,
    int wbase, const float* __restrict__ bias)
{
    const float* __restrict__ A = (asel < 0) ? Aext : g_feat;
    int hf = blockIdx.y;    // 0 -> lbufH (Wl, half out), 1 -> rbuf (Wr, +bias, fp32 out)
    const float* __restrict__ BT = g_WT[wbase + hf];

    __shared__ float As[16][128];
    __shared__ float Bs[16][128];

    int tid = threadIdx.x;
    int tx = tid & 15;
    int ty = tid >> 4;
    int m0 = blockIdx.x * 128;

    uint64_t acc[8][4];
    uint64_t z = splat2(0.f);
#pragma unroll
    for (int i = 0; i < 8; i++)
#pragma unroll
        for (int j = 0; j < 4; j++) acc[i][j] = z;

    int arow = tid & 127;
    int akq0 = tid >> 7;
    int bj   = (tid & 31) * 4;
    int bk0  = tid >> 5;

    for (int k0 = 0; k0 < 128; k0 += 16) {
#pragma unroll
        for (int p = 0; p < 2; p++) {
            int kq = akq0 + p * 2;
            int grow = m0 + arow;
            float4 v = make_float4(0.f, 0.f, 0.f, 0.f);
            if (grow < NN)
                v = *(const float4*)(A + (size_t)grow * HID + k0 + kq * 4);
            As[kq * 4 + 0][arow] = v.x;
            As[kq * 4 + 1][arow] = v.y;
            As[kq * 4 + 2][arow] = v.z;
            As[kq * 4 + 3][arow] = v.w;
        }
#pragma unroll
        for (int p = 0; p < 2; p++) {
            int kr = bk0 + p * 8;
            *(float4*)&Bs[kr][bj] = *(const float4*)(BT + (size_t)(k0 + kr) * HID + bj);
        }
        __syncthreads();
#pragma unroll
        for (int kk = 0; kk < 16; kk++) {
            float a[8];
            *(float4*)&a[0] = *(const float4*)&As[kk][ty * 8];
            *(float4*)&a[4] = *(const float4*)&As[kk][ty * 8 + 4];
            float4 bl = *(const float4*)&Bs[kk][tx * 4];
            float4 bh = *(const float4*)&Bs[kk][64 + tx * 4];
            uint64_t bp[4];
            bp[0] = pk2(bl.x, bl.y); bp[1] = pk2(bl.z, bl.w);
            bp[2] = pk2(bh.x, bh.y); bp[3] = pk2(bh.z, bh.w);
#pragma unroll
            for (int i = 0; i < 8; i++) {
                uint64_t as_ = splat2(a[i]);
                ffma2(acc[i][0], as_, bp[0]);
                ffma2(acc[i][1], as_, bp[1]);
                ffma2(acc[i][2], as_, bp[2]);
                ffma2(acc[i][3], as_, bp[3]);
            }
        }
        __syncthreads();
    }

    float bv0[4], bv1[4];
#pragma unroll
    for (int j = 0; j < 4; j++) {
        bv0[j] = hf ? bias[tx * 4 + j] : 0.f;
        bv1[j] = hf ? bias[64 + tx * 4 + j] : 0.f;
    }
#pragma unroll
    for (int i = 0; i < 8; i++) {
        int grow = m0 + ty * 8 + i;
        if (grow >= NN) continue;
        float2 p0 = unpk2(acc[i][0]), p1 = unpk2(acc[i][1]);
        float2 p2 = unpk2(acc[i][2]), p3 = unpk2(acc[i][3]);
        float4 v0 = make_float4(p0.x + bv0[0], p0.y + bv0[1], p1.x + bv0[2], p1.y + bv0[3]);
        float4 v1 = make_float4(p2.x + bv1[0], p2.y + bv1[1], p3.x + bv1[2], p3.y + bv1[3]);
        if (hf) {
            *(float4*)(g_rbuf + (size_t)grow * HID + tx * 4)      = v0;
            *(float4*)(g_rbuf + (size_t)grow * HID + 64 + tx * 4) = v1;
        } else {
            *(uint2*)(g_lbufH + (size_t)grow * HID + tx * 4)      = f4_to_h4(v0);
            *(uint2*)(g_lbufH + (size_t)grow * HID + 64 + tx * 4) = f4_to_h4(v1);
        }
    }
}

// ---------------- fused aggregate + self + relu: feat = relu(sum lbufH[src] + rbuf[w]) ----------------
__global__ void k_agg2() {
    int w    = (blockIdx.x * blockDim.x + threadIdx.x) >> 5;
    int lane = threadIdx.x & 31;
    if (w >= NN) return;
    int beg = g_rowptr[w], end = g_rowptr[w + 1];
    float4 acc = *(const float4*)(g_rbuf + (size_t)w * HID + lane * 4);
    int e = beg;
    for (; e + 3 < end; e += 4) {
        int s0 = g_csr_src[e], s1 = g_csr_src[e + 1];
        int s2 = g_csr_src[e + 2], s3 = g_csr_src[e + 3];
        float4 v0 = h4_to_f4(*(const uint2*)(g_lbufH + (size_t)s0 * HID + lane * 4));
        float4 v1 = h4_to_f4(*(const uint2*)(g_lbufH + (size_t)s1 * HID + lane * 4));
        float4 v2 = h4_to_f4(*(const uint2*)(g_lbufH + (size_t)s2 * HID + lane * 4));
        float4 v3 = h4_to_f4(*(const uint2*)(g_lbufH + (size_t)s3 * HID + lane * 4));
        acc.x += (v0.x + v1.x) + (v2.x + v3.x);
        acc.y += (v0.y + v1.y) + (v2.y + v3.y);
        acc.z += (v0.z + v1.z) + (v2.z + v3.z);
        acc.w += (v0.w + v1.w) + (v2.w + v3.w);
    }
    for (; e < end; e++) {
        int s0 = g_csr_src[e];
        float4 v0 = h4_to_f4(*(const uint2*)(g_lbufH + (size_t)s0 * HID + lane * 4));
        acc.x += v0.x; acc.y += v0.y; acc.z += v0.z; acc.w += v0.w;
    }
    acc.x = fmaxf(acc.x, 0.f); acc.y = fmaxf(acc.y, 0.f);
    acc.z = fmaxf(acc.z, 0.f); acc.w = fmaxf(acc.w, 0.f);
    *(float4*)(g_feat + (size_t)w * HID + lane * 4) = acc;
}

// ---------------- layer-3 collapsed per-graph reduction (fp32 feat, NPW=16) ----------------
__global__ void k_pool3(const int* __restrict__ batch) {
    const float* __restrict__ h = g_feat;
    const int NPW = 16;
    int w    = (blockIdx.x * blockDim.x + threadIdx.x) >> 5;
    int lane = threadIdx.x & 31;
    int n0 = w * NPW;
    if (n0 >= NN) return;
    int n1 = min(n0 + NPW, NN);

    float4 aS = make_float4(0.f, 0.f, 0.f, 0.f);
    float4 aA = make_float4(0.f, 0.f, 0.f, 0.f);
    int cg = -1, cnt = 0;
    for (int n = n0; n < n1; n++) {
        int g = batch[n];
        if (g != cg) {
            if (cg >= 0) {
                float* ps = g_Pself + cg * HID + lane * 4;
                float* pa = g_Pagg  + cg * HID + lane * 4;
                atomicAdd(ps + 0, aS.x); atomicAdd(ps + 1, aS.y);
                atomicAdd(ps + 2, aS.z); atomicAdd(ps + 3, aS.w);
                atomicAdd(pa + 0, aA.x); atomicAdd(pa + 1, aA.y);
                atomicAdd(pa + 2, aA.z); atomicAdd(pa + 3, aA.w);
                if (lane == 0) atomicAdd(&g_cnt[cg], (float)cnt);
            }
            cg = g; cnt = 0;
            aS = make_float4(0.f, 0.f, 0.f, 0.f);
            aA = make_float4(0.f, 0.f, 0.f, 0.f);
        }
        float4 v = *(const float4*)(h + (size_t)n * HID + lane * 4);
        aS.x += v.x; aS.y += v.y; aS.z += v.z; aS.w += v.w;
        cnt++;
        int beg = g_rowptr[n], end = g_rowptr[n + 1];
        int e = beg;
        for (; e + 3 < end; e += 4) {
            int s0 = g_csr_src[e], s1 = g_csr_src[e + 1];
            int s2 = g_csr_src[e + 2], s3 = g_csr_src[e + 3];
            float4 u0 = *(const float4*)(h + (size_t)s0 * HID + lane * 4);
            float4 u1 = *(const float4*)(h + (size_t)s1 * HID + lane * 4);
            float4 u2 = *(const float4*)(h + (size_t)s2 * HID + lane * 4);
            float4 u3 = *(const float4*)(h + (size_t)s3 * HID + lane * 4);
            aA.x += (u0.x + u1.x) + (u2.x + u3.x);
            aA.y += (u0.y + u1.y) + (u2.y + u3.y);
            aA.z += (u0.z + u1.z) + (u2.z + u3.z);
            aA.w += (u0.w + u1.w) + (u2.w + u3.w);
        }
        for (; e < end; e++) {
            int s0 = g_csr_src[e];
            float4 u0 = *(const float4*)(h + (size_t)s0 * HID + lane * 4);
            aA.x += u0.x; aA.y += u0.y; aA.z += u0.z; aA.w += u0.w;
        }
    }
    if (cg >= 0) {
        float* ps = g_Pself + cg * HID + lane * 4;
        float* pa = g_Pagg  + cg * HID + lane * 4;
        atomicAdd(ps + 0, aS.x); atomicAdd(ps + 1, aS.y);
        atomicAdd(ps + 2, aS.z); atomicAdd(ps + 3, aS.w);
        atomicAdd(pa + 0, aA.x); atomicAdd(pa + 1, aA.y);
        atomicAdd(pa + 2, aA.z); atomicAdd(pa + 3, aA.w);
        if (lane == 0) atomicAdd(&g_cnt[cg], (float)cnt);
    }
}

// ---------------- final: pooled = (Pagg@W3l^T + cnt*b3l + Pself@W3r^T)/cnt ; out = pooled@Wlin^T + blin
__global__ void k_final3(const float* __restrict__ W3l, const float* __restrict__ b3l,
                         const float* __restrict__ W3r,
                         const float* __restrict__ Wlin, const float* __restrict__ blin,
                         float* __restrict__ out) {
    __shared__ float sA[HID], sS[HID], sP[HID];
    int g = blockIdx.x, t = threadIdx.x;
    sA[t] = g_Pagg [g * HID + t];
    sS[t] = g_Pself[g * HID + t];
    __syncthreads();
    float cnt = g_cnt[g];
    float inv = 1.f / fmaxf(cnt, 1.f);
    float s = cnt * b3l[t];
    const float* wl = W3l + t * HID;
    const float* wr = W3r + t * HID;
#pragma unroll
    for (int k = 0; k < HID; k++) s = fmaf(sA[k], wl[k], fmaf(sS[k], wr[k], s));
    sP[t] = s * inv;
    __syncthreads();
    if (t < ODIM) {
        float o = blin[t];
        const float* wf = Wlin + t * HID;
#pragma unroll
        for (int k = 0; k < HID; k++) o = fmaf(sP[k], wf[k], o);
        out[g * ODIM + t] = o;
    }
}

// ---------------- launch (fork-join capture: CSR build overlaps GEMM-1) ----------------
static cudaStream_t g_s2 = nullptr;
static cudaEvent_t  g_e0 = nullptr, g_e2 = nullptr;

extern "C" void kernel_launch(void* const* d_in, const int* in_sizes, int n_in,
                              void* d_out, int out_size) {
    const float* x    = (const float*)d_in[0];
    const int*   ei   = (const int*)d_in[1];
    const int*   batch= (const int*)d_in[2];
    const float* W1l  = (const float*)d_in[3];
    const float* b1l  = (const float*)d_in[4];
    const float* W1r  = (const float*)d_in[5];
    const float* W2l  = (const float*)d_in[6];
    const float* b2l  = (const float*)d_in[7];
    const float* W2r  = (const float*)d_in[8];
    const float* W3l  = (const float*)d_in[9];
    const float* b3l  = (const float*)d_in[10];
    const float* W3r  = (const float*)d_in[11];
    const float* Wlin = (const float*)d_in[12];
    const float* blin = (const float*)d_in[13];
    float* out = (float*)d_out;

    const int* src = ei;
    const int* dst = ei + EE;

    if (!g_s2) {
        cudaStreamCreateWithFlags(&g_s2, cudaStreamNonBlocking);
        cudaEventCreateWithFlags(&g_e0, cudaEventDisableTiming);
        cudaEventCreateWithFlags(&g_e2, cudaEventDisableTiming);
    }

    const int ZB = (NN + 255) / 256;

    // fork: side stream builds CSR while main stream runs transposes + GEMM-1
    cudaEventRecord(g_e0, 0);
    cudaStreamWaitEvent(g_s2, g_e0, 0);
    k_zero2<<<ZB, 256, 0, g_s2>>>();
    k_hist<<<(EE / 4 + 255) / 256, 256, 0, g_s2>>>(dst);
    k_scan<<<1, 1024, 0, g_s2>>>();
    k_bin<<<(EE / 2 + 255) / 256, 256, 0, g_s2>>>(src, dst);
    cudaEventRecord(g_e2, g_s2);

    dim3 gemm_grid((NN + 127) / 128, 2);
    const int AGG_B = (NN * 32 + 255) / 256;

    k_tr<<<256, 256>>>(W1l, W1r, W2l, W2r);
    k_gemm<<<gemm_grid, 256>>>(x, -1, 0, b1l);

    // join: aggregation needs the CSR
    cudaStreamWaitEvent(0, g_e2, 0);
    k_agg2<<<AGG_B, 256>>>();
    k_gemm<<<gemm_grid, 256>>>(nullptr, 0, 2, b2l);
    k_agg2<<<AGG_B, 256>>>();

    const int POOL_W = (NN + 15) / 16;
    const int POOL_B = (POOL_W * 32 + 255) / 256;
    k_pool3<<<POOL_B, 256>>>(batch);
    k_final3<<<NG, HID>>>(W3l, b3l, W3r, Wlin, blin, out);
}

// round 17
// speedup vs baseline: 1.2336x; 1.0103x over previous
#include <cuda_runtime.h>
#include <cuda_fp16.h>
#include <cstdint>

#define NN   50000
#define EE   800000
#define HID  128
#define NG   64
#define ODIM 64

// ---------------- device scratch (no allocations allowed) ----------------
__device__ __half g_lbufH[NN * HID];  // x @ Wl^T, fp16 transport (random-gathered over edges)
__device__ float  g_rbuf[NN * HID];   // x @ Wr^T + b, fp32
__device__ float  g_feat[NN * HID];   // activations, fp32
__device__ int    g_deg[NN];
__device__ int    g_rowptr[NN + 1];
__device__ int    g_cursor[NN];
__device__ int    g_csr_src[EE];
__device__ float  g_WT[4][HID * HID]; // transposed weights [in][out]: W1l,W1r,W2l,W2r
__device__ float  g_Pagg [NG * HID];
__device__ float  g_Pself[NG * HID];
__device__ float  g_cnt[NG];

// ---------------- packed f32x2 / half helpers ----------------
__device__ __forceinline__ uint64_t splat2(float v) {
    uint64_t r;
    asm("mov.b64 %0, {%1, %1};" : "=l"(r) : "f"(v));
    return r;
}
__device__ __forceinline__ uint64_t pk2(float x, float y) {
    uint64_t r;
    asm("mov.b64 %0, {%1, %2};" : "=l"(r) : "f"(x), "f"(y));
    return r;
}
__device__ __forceinline__ void ffma2(uint64_t& d, uint64_t a, uint64_t b) {
    asm("fma.rn.f32x2 %0, %1, %2, %0;" : "+l"(d) : "l"(a), "l"(b));
}
__device__ __forceinline__ float2 unpk2(uint64_t v) {
    float x, y;
    asm("mov.b64 {%0, %1}, %2;" : "=f"(x), "=f"(y) : "l"(v));
    return make_float2(x, y);
}
__device__ __forceinline__ float4 h4_to_f4(uint2 u) {
    __half2 h0 = *(__half2*)&u.x, h1 = *(__half2*)&u.y;
    float2 f0 = __half22float2(h0), f1 = __half22float2(h1);
    return make_float4(f0.x, f0.y, f1.x, f1.y);
}
__device__ __forceinline__ uint2 f4_to_h4(float4 v) {
    union { __half2 h[2]; uint2 u; } c;
    c.h[0] = __floats2half2_rn(v.x, v.y);
    c.h[1] = __floats2half2_rn(v.z, v.w);
    return c.u;
}

// ---------------- weight transposes: W1 pair on main (critical), W2 pair hidden ----------------
__global__ void k_tr1(const float* __restrict__ W1l, const float* __restrict__ W1r) {
    int i = blockIdx.x * blockDim.x + threadIdx.x;   // 32768 threads
    int idx = i >> 14;                               // 0 or 1
    int r = i & (HID * HID - 1);
    int o = r / HID, k = r % HID;
    const float* W = (idx == 0) ? W1l : W1r;
    g_WT[idx][k * HID + o] = W[o * HID + k];
}
__global__ void k_tr2(const float* __restrict__ W2l, const float* __restrict__ W2r) {
    int i = blockIdx.x * blockDim.x + threadIdx.x;   // 32768 threads
    int idx = i >> 14;                               // 0 or 1
    int r = i & (HID * HID - 1);
    int o = r / HID, k = r % HID;
    const float* W = (idx == 0) ? W2l : W2r;
    g_WT[2 + idx][k * HID + o] = W[o * HID + k];
}

// ---------------- zero counters (side stream) ----------------
__global__ void k_zero2() {
    int i = blockIdx.x * blockDim.x + threadIdx.x;
    if (i < NN) g_deg[i] = 0;
    if (i < NG * HID) { g_Pagg[i] = 0.f; g_Pself[i] = 0.f; }
    if (i < NG) g_cnt[i] = 0.f;
}

__global__ void k_hist(const int* __restrict__ dst) {
    int t = blockIdx.x * blockDim.x + threadIdx.x;
    int e = t * 4;
    if (e + 3 < EE) {
        int4 d = *(const int4*)(dst + e);
        atomicAdd(&g_deg[d.x], 1);
        atomicAdd(&g_deg[d.y], 1);
        atomicAdd(&g_deg[d.z], 1);
        atomicAdd(&g_deg[d.w], 1);
    } else {
        for (int q = e; q < EE; q++) atomicAdd(&g_deg[dst[q]], 1);
    }
}

__global__ void k_scan() {
    __shared__ int ssum[1024];
    int tid = threadIdx.x;
    const int CH = (NN + 1023) / 1024;
    int base = tid * CH;
    int s = 0;
    for (int i = 0; i < CH; i++) { int idx = base + i; if (idx < NN) s += g_deg[idx]; }
    ssum[tid] = s;
    __syncthreads();
    for (int off = 1; off < 1024; off <<= 1) {
        int v = (tid >= off) ? ssum[tid - off] : 0;
        __syncthreads();
        ssum[tid] += v;
        __syncthreads();
    }
    int run = (tid == 0) ? 0 : ssum[tid - 1];
    for (int i = 0; i < CH; i++) {
        int idx = base + i;
        if (idx < NN) { g_rowptr[idx] = run; g_cursor[idx] = run; run += g_deg[idx]; }
    }
    if (tid == 1023) g_rowptr[NN] = run;
}

__global__ void k_bin(const int* __restrict__ src, const int* __restrict__ dst) {
    int t = blockIdx.x * blockDim.x + threadIdx.x;
    int e = t * 2;
    if (e + 1 < EE) {
        int2 s = *(const int2*)(src + e);
        int2 d = *(const int2*)(dst + e);
        int p0 = atomicAdd(&g_cursor[d.x], 1);
        g_csr_src[p0] = s.x;
        int p1 = atomicAdd(&g_cursor[d.y], 1);
        g_csr_src[p1] = s.y;
    } else if (e < EE) {
        int p = atomicAdd(&g_cursor[dst[e]], 1);
        g_csr_src[p] = src[e];
    }
}

// ---------------- fp32 GEMM: [lbufH | rbuf] = A @ WT (+bias on rbuf half) ----------------
// M=NN, N=128 per half, K=128. Block tile 128x128, 256 threads, 8x8/thread.
__global__ __launch_bounds__(256) void k_gemm(
    const float* __restrict__ Aext, int asel,
    int wbase, const float* __restrict__ bias)
{
    const float* __restrict__ A = (asel < 0) ? Aext : g_feat;
    int hf = blockIdx.y;    // 0 -> lbufH (Wl, half out), 1 -> rbuf (Wr, +bias, fp32 out)
    const float* __restrict__ BT = g_WT[wbase + hf];

    __shared__ float As[16][128];
    __shared__ float Bs[16][128];

    int tid = threadIdx.x;
    int tx = tid & 15;
    int ty = tid >> 4;
    int m0 = blockIdx.x * 128;

    uint64_t acc[8][4];
    uint64_t z = splat2(0.f);
#pragma unroll
    for (int i = 0; i < 8; i++)
#pragma unroll
        for (int j = 0; j < 4; j++) acc[i][j] = z;

    int arow = tid & 127;
    int akq0 = tid >> 7;
    int bj   = (tid & 31) * 4;
    int bk0  = tid >> 5;

    for (int k0 = 0; k0 < 128; k0 += 16) {
#pragma unroll
        for (int p = 0; p < 2; p++) {
            int kq = akq0 + p * 2;
            int grow = m0 + arow;
            float4 v = make_float4(0.f, 0.f, 0.f, 0.f);
            if (grow < NN)
                v = *(const float4*)(A + (size_t)grow * HID + k0 + kq * 4);
            As[kq * 4 + 0][arow] = v.x;
            As[kq * 4 + 1][arow] = v.y;
            As[kq * 4 + 2][arow] = v.z;
            As[kq * 4 + 3][arow] = v.w;
        }
#pragma unroll
        for (int p = 0; p < 2; p++) {
            int kr = bk0 + p * 8;
            *(float4*)&Bs[kr][bj] = *(const float4*)(BT + (size_t)(k0 + kr) * HID + bj);
        }
        __syncthreads();
#pragma unroll
        for (int kk = 0; kk < 16; kk++) {
            float a[8];
            *(float4*)&a[0] = *(const float4*)&As[kk][ty * 8];
            *(float4*)&a[4] = *(const float4*)&As[kk][ty * 8 + 4];
            float4 bl = *(const float4*)&Bs[kk][tx * 4];
            float4 bh = *(const float4*)&Bs[kk][64 + tx * 4];
            uint64_t bp[4];
            bp[0] = pk2(bl.x, bl.y); bp[1] = pk2(bl.z, bl.w);
            bp[2] = pk2(bh.x, bh.y); bp[3] = pk2(bh.z, bh.w);
#pragma unroll
            for (int i = 0; i < 8; i++) {
                uint64_t as_ = splat2(a[i]);
                ffma2(acc[i][0], as_, bp[0]);
                ffma2(acc[i][1], as_, bp[1]);
                ffma2(acc[i][2], as_, bp[2]);
                ffma2(acc[i][3], as_, bp[3]);
            }
        }
        __syncthreads();
    }

    float bv0[4], bv1[4];
#pragma unroll
    for (int j = 0; j < 4; j++) {
        bv0[j] = hf ? bias[tx * 4 + j] : 0.f;
        bv1[j] = hf ? bias[64 + tx * 4 + j] : 0.f;
    }
#pragma unroll
    for (int i = 0; i < 8; i++) {
        int grow = m0 + ty * 8 + i;
        if (grow >= NN) continue;
        float2 p0 = unpk2(acc[i][0]), p1 = unpk2(acc[i][1]);
        float2 p2 = unpk2(acc[i][2]), p3 = unpk2(acc[i][3]);
        float4 v0 = make_float4(p0.x + bv0[0], p0.y + bv0[1], p1.x + bv0[2], p1.y + bv0[3]);
        float4 v1 = make_float4(p2.x + bv1[0], p2.y + bv1[1], p3.x + bv1[2], p3.y + bv1[3]);
        if (hf) {
            *(float4*)(g_rbuf + (size_t)grow * HID + tx * 4)      = v0;
            *(float4*)(g_rbuf + (size_t)grow * HID + 64 + tx * 4) = v1;
        } else {
            *(uint2*)(g_lbufH + (size_t)grow * HID + tx * 4)      = f4_to_h4(v0);
            *(uint2*)(g_lbufH + (size_t)grow * HID + 64 + tx * 4) = f4_to_h4(v1);
        }
    }
}

// ---------------- fused aggregate + self + relu (unroll 8 -> 4 -> 1) ----------------
__global__ void k_agg2() {
    int w    = (blockIdx.x * blockDim.x + threadIdx.x) >> 5;
    int lane = threadIdx.x & 31;
    if (w >= NN) return;
    int beg = g_rowptr[w], end = g_rowptr[w + 1];
    float4 acc = *(const float4*)(g_rbuf + (size_t)w * HID + lane * 4);
    int e = beg;
    for (; e + 7 < end; e += 8) {
        int s0 = g_csr_src[e],     s1 = g_csr_src[e + 1];
        int s2 = g_csr_src[e + 2], s3 = g_csr_src[e + 3];
        int s4 = g_csr_src[e + 4], s5 = g_csr_src[e + 5];
        int s6 = g_csr_src[e + 6], s7 = g_csr_src[e + 7];
        float4 v0 = h4_to_f4(*(const uint2*)(g_lbufH + (size_t)s0 * HID + lane * 4));
        float4 v1 = h4_to_f4(*(const uint2*)(g_lbufH + (size_t)s1 * HID + lane * 4));
        float4 v2 = h4_to_f4(*(const uint2*)(g_lbufH + (size_t)s2 * HID + lane * 4));
        float4 v3 = h4_to_f4(*(const uint2*)(g_lbufH + (size_t)s3 * HID + lane * 4));
        float4 v4 = h4_to_f4(*(const uint2*)(g_lbufH + (size_t)s4 * HID + lane * 4));
        float4 v5 = h4_to_f4(*(const uint2*)(g_lbufH + (size_t)s5 * HID + lane * 4));
        float4 v6 = h4_to_f4(*(const uint2*)(g_lbufH + (size_t)s6 * HID + lane * 4));
        float4 v7 = h4_to_f4(*(const uint2*)(g_lbufH + (size_t)s7 * HID + lane * 4));
        acc.x += ((v0.x + v1.x) + (v2.x + v3.x)) + ((v4.x + v5.x) + (v6.x + v7.x));
        acc.y += ((v0.y + v1.y) + (v2.y + v3.y)) + ((v4.y + v5.y) + (v6.y + v7.y));
        acc.z += ((v0.z + v1.z) + (v2.z + v3.z)) + ((v4.z + v5.z) + (v6.z + v7.z));
        acc.w += ((v0.w + v1.w) + (v2.w + v3.w)) + ((v4.w + v5.w) + (v6.w + v7.w));
    }
    for (; e + 3 < end; e += 4) {
        int s0 = g_csr_src[e],     s1 = g_csr_src[e + 1];
        int s2 = g_csr_src[e + 2], s3 = g_csr_src[e + 3];
        float4 v0 = h4_to_f4(*(const uint2*)(g_lbufH + (size_t)s0 * HID + lane * 4));
        float4 v1 = h4_to_f4(*(const uint2*)(g_lbufH + (size_t)s1 * HID + lane * 4));
        float4 v2 = h4_to_f4(*(const uint2*)(g_lbufH + (size_t)s2 * HID + lane * 4));
        float4 v3 = h4_to_f4(*(const uint2*)(g_lbufH + (size_t)s3 * HID + lane * 4));
        acc.x += (v0.x + v1.x) + (v2.x + v3.x);
        acc.y += (v0.y + v1.y) + (v2.y + v3.y);
        acc.z += (v0.z + v1.z) + (v2.z + v3.z);
        acc.w += (v0.w + v1.w) + (v2.w + v3.w);
    }
    for (; e < end; e++) {
        int s0 = g_csr_src[e];
        float4 v0 = h4_to_f4(*(const uint2*)(g_lbufH + (size_t)s0 * HID + lane * 4));
        acc.x += v0.x; acc.y += v0.y; acc.z += v0.z; acc.w += v0.w;
    }
    acc.x = fmaxf(acc.x, 0.f); acc.y = fmaxf(acc.y, 0.f);
    acc.z = fmaxf(acc.z, 0.f); acc.w = fmaxf(acc.w, 0.f);
    *(float4*)(g_feat + (size_t)w * HID + lane * 4) = acc;
}

// ---------------- layer-3 collapsed per-graph reduction (fp32 feat, NPW=16, unroll 8) ----------------
__global__ void k_pool3(const int* __restrict__ batch) {
    const float* __restrict__ h = g_feat;
    const int NPW = 16;
    int w    = (blockIdx.x * blockDim.x + threadIdx.x) >> 5;
    int lane = threadIdx.x & 31;
    int n0 = w * NPW;
    if (n0 >= NN) return;
    int n1 = min(n0 + NPW, NN);

    float4 aS = make_float4(0.f, 0.f, 0.f, 0.f);
    float4 aA = make_float4(0.f, 0.f, 0.f, 0.f);
    int cg = -1, cnt = 0;
    for (int n = n0; n < n1; n++) {
        int g = batch[n];
        if (g != cg) {
            if (cg >= 0) {
                float* ps = g_Pself + cg * HID + lane * 4;
                float* pa = g_Pagg  + cg * HID + lane * 4;
                atomicAdd(ps + 0, aS.x); atomicAdd(ps + 1, aS.y);
                atomicAdd(ps + 2, aS.z); atomicAdd(ps + 3, aS.w);
                atomicAdd(pa + 0, aA.x); atomicAdd(pa + 1, aA.y);
                atomicAdd(pa + 2, aA.z); atomicAdd(pa + 3, aA.w);
                if (lane == 0) atomicAdd(&g_cnt[cg], (float)cnt);
            }
            cg = g; cnt = 0;
            aS = make_float4(0.f, 0.f, 0.f, 0.f);
            aA = make_float4(0.f, 0.f, 0.f, 0.f);
        }
        float4 v = *(const float4*)(h + (size_t)n * HID + lane * 4);
        aS.x += v.x; aS.y += v.y; aS.z += v.z; aS.w += v.w;
        cnt++;
        int beg = g_rowptr[n], end = g_rowptr[n + 1];
        int e = beg;
        for (; e + 7 < end; e += 8) {
            int s0 = g_csr_src[e],     s1 = g_csr_src[e + 1];
            int s2 = g_csr_src[e + 2], s3 = g_csr_src[e + 3];
            int s4 = g_csr_src[e + 4], s5 = g_csr_src[e + 5];
            int s6 = g_csr_src[e + 6], s7 = g_csr_src[e + 7];
            float4 u0 = *(const float4*)(h + (size_t)s0 * HID + lane * 4);
            float4 u1 = *(const float4*)(h + (size_t)s1 * HID + lane * 4);
            float4 u2 = *(const float4*)(h + (size_t)s2 * HID + lane * 4);
            float4 u3 = *(const float4*)(h + (size_t)s3 * HID + lane * 4);
            float4 u4 = *(const float4*)(h + (size_t)s4 * HID + lane * 4);
            float4 u5 = *(const float4*)(h + (size_t)s5 * HID + lane * 4);
            float4 u6 = *(const float4*)(h + (size_t)s6 * HID + lane * 4);
            float4 u7 = *(const float4*)(h + (size_t)s7 * HID + lane * 4);
            aA.x += ((u0.x + u1.x) + (u2.x + u3.x)) + ((u4.x + u5.x) + (u6.x + u7.x));
            aA.y += ((u0.y + u1.y) + (u2.y + u3.y)) + ((u4.y + u5.y) + (u6.y + u7.y));
            aA.z += ((u0.z + u1.z) + (u2.z + u3.z)) + ((u4.z + u5.z) + (u6.z + u7.z));
            aA.w += ((u0.w + u1.w) + (u2.w + u3.w)) + ((u4.w + u5.w) + (u6.w + u7.w));
        }
        for (; e + 3 < end; e += 4) {
            int s0 = g_csr_src[e],     s1 = g_csr_src[e + 1];
            int s2 = g_csr_src[e + 2], s3 = g_csr_src[e + 3];
            float4 u0 = *(const float4*)(h + (size_t)s0 * HID + lane * 4);
            float4 u1 = *(const float4*)(h + (size_t)s1 * HID + lane * 4);
            float4 u2 = *(const float4*)(h + (size_t)s2 * HID + lane * 4);
            float4 u3 = *(const float4*)(h + (size_t)s3 * HID + lane * 4);
            aA.x += (u0.x + u1.x) + (u2.x + u3.x);
            aA.y += (u0.y + u1.y) + (u2.y + u3.y);
            aA.z += (u0.z + u1.z) + (u2.z + u3.z);
            aA.w += (u0.w + u1.w) + (u2.w + u3.w);
        }
        for (; e < end; e++) {
            int s0 = g_csr_src[e];
            float4 u0 = *(const float4*)(h + (size_t)s0 * HID + lane * 4);
            aA.x += u0.x; aA.y += u0.y; aA.z += u0.z; aA.w += u0.w;
        }
    }
    if (cg >= 0) {
        float* ps = g_Pself + cg * HID + lane * 4;
        float* pa = g_Pagg  + cg * HID + lane * 4;
        atomicAdd(ps + 0, aS.x); atomicAdd(ps + 1, aS.y);
        atomicAdd(ps + 2, aS.z); atomicAdd(ps + 3, aS.w);
        atomicAdd(pa + 0, aA.x); atomicAdd(pa + 1, aA.y);
        atomicAdd(pa + 2, aA.z); atomicAdd(pa + 3, aA.w);
        if (lane == 0) atomicAdd(&g_cnt[cg], (float)cnt);
    }
}

// ---------------- final: pooled = (Pagg@W3l^T + cnt*b3l + Pself@W3r^T)/cnt ; out = pooled@Wlin^T + blin
__global__ void k_final3(const float* __restrict__ W3l, const float* __restrict__ b3l,
                         const float* __restrict__ W3r,
                         const float* __restrict__ Wlin, const float* __restrict__ blin,
                         float* __restrict__ out) {
    __shared__ float sA[HID], sS[HID], sP[HID];
    int g = blockIdx.x, t = threadIdx.x;
    sA[t] = g_Pagg [g * HID + t];
    sS[t] = g_Pself[g * HID + t];
    __syncthreads();
    float cnt = g_cnt[g];
    float inv = 1.f / fmaxf(cnt, 1.f);
    float s = cnt * b3l[t];
    const float* wl = W3l + t * HID;
    const float* wr = W3r + t * HID;
#pragma unroll
    for (int k = 0; k < HID; k++) s = fmaf(sA[k], wl[k], fmaf(sS[k], wr[k], s));
    sP[t] = s * inv;
    __syncthreads();
    if (t < ODIM) {
        float o = blin[t];
        const float* wf = Wlin + t * HID;
#pragma unroll
        for (int k = 0; k < HID; k++) o = fmaf(sP[k], wf[k], o);
        out[g * ODIM + t] = o;
    }
}

// ---------------- launch (fork-join capture: CSR build + W2 transposes overlap GEMM-1) ----------------
static cudaStream_t g_s2 = nullptr;
static cudaEvent_t  g_e0 = nullptr, g_e2 = nullptr;

extern "C" void kernel_launch(void* const* d_in, const int* in_sizes, int n_in,
                              void* d_out, int out_size) {
    const float* x    = (const float*)d_in[0];
    const int*   ei   = (const int*)d_in[1];
    const int*   batch= (const int*)d_in[2];
    const float* W1l  = (const float*)d_in[3];
    const float* b1l  = (const float*)d_in[4];
    const float* W1r  = (const float*)d_in[5];
    const float* W2l  = (const float*)d_in[6];
    const float* b2l  = (const float*)d_in[7];
    const float* W2r  = (const float*)d_in[8];
    const float* W3l  = (const float*)d_in[9];
    const float* b3l  = (const float*)d_in[10];
    const float* W3r  = (const float*)d_in[11];
    const float* Wlin = (const float*)d_in[12];
    const float* blin = (const float*)d_in[13];
    float* out = (float*)d_out;

    const int* src = ei;
    const int* dst = ei + EE;

    if (!g_s2) {
        cudaStreamCreateWithFlags(&g_s2, cudaStreamNonBlocking);
        cudaEventCreateWithFlags(&g_e0, cudaEventDisableTiming);
        cudaEventCreateWithFlags(&g_e2, cudaEventDisableTiming);
    }

    const int ZB = (NN + 255) / 256;

    // fork: side stream builds CSR + W2 transposes while main runs tr1 + GEMM-1
    cudaEventRecord(g_e0, 0);
    cudaStreamWaitEvent(g_s2, g_e0, 0);
    k_zero2<<<ZB, 256, 0, g_s2>>>();
    k_hist<<<(EE / 4 + 255) / 256, 256, 0, g_s2>>>(dst);
    k_scan<<<1, 1024, 0, g_s2>>>();
    k_bin<<<(EE / 2 + 255) / 256, 256, 0, g_s2>>>(src, dst);
    k_tr2<<<128, 256, 0, g_s2>>>(W2l, W2r);          // hidden under GEMM-1
    cudaEventRecord(g_e2, g_s2);

    dim3 gemm_grid((NN + 127) / 128, 2);
    const int AGG_B = (NN * 32 + 255) / 256;

    k_tr1<<<128, 256>>>(W1l, W1r);
    k_gemm<<<gemm_grid, 256>>>(x, -1, 0, b1l);

    // join: aggregation needs the CSR; GEMM-2 needs W2 transposes (also behind e2)
    cudaStreamWaitEvent(0, g_e2, 0);
    k_agg2<<<AGG_B, 256>>>();
    k_gemm<<<gemm_grid, 256>>>(nullptr, 0, 2, b2l);
    k_agg2<<<AGG_B, 256>>>();

    const int POOL_W = (NN + 15) / 16;
    const int POOL_B = (POOL_W * 32 + 255) / 256;
    k_pool3<<<POOL_B, 256>>>(batch);
    k_final3<<<NG, HID>>>(W3l, b3l, W3r, Wlin, blin, out);
}